// round 13
// baseline (speedup 1.0000x reference)
#include <cuda_runtime.h>
#include <math.h>

#define BB 8
#define CC 256
#define HH 56
#define WW 56
#define HW (HH*WW)          // 3136
#define KK 3
#define TAPS 9
#define MID 51
#define CKK (CC*TAPS)       // 2304
#define GAIN_OVER_K 0.4714045207910317f   // sqrt(2)/3

__device__ __align__(16) float g_pooled[BB * CC];
__device__ __align__(16) float g_sf[BB * TAPS * HW];
__device__ __align__(16) float g_cf[BB * CKK];
__device__ unsigned g_pcnt[BB] = {0};   // monotonic per-batch arrival counter

typedef unsigned long long ull;

// ---- f32x2 packed helpers (sm_103a) --------------------------------------
__device__ __forceinline__ ull pack2(float x, float y) {
    ull r; asm("mov.b64 %0, {%1, %2};" : "=l"(r) : "f"(x), "f"(y)); return r;
}
__device__ __forceinline__ void unpack2(ull v, float& x, float& y) {
    asm("mov.b64 {%0, %1}, %2;" : "=f"(x), "=f"(y) : "l"(v));
}
__device__ __forceinline__ ull mul2(ull a, ull b) {
    ull d; asm("mul.rn.f32x2 %0, %1, %2;" : "=l"(d) : "l"(a), "l"(b)); return d;
}
__device__ __forceinline__ ull fma2(ull a, ull b, ull c) {
    ull d; asm("fma.rn.f32x2 %0, %1, %2, %3;" : "=l"(d) : "l"(a), "l"(b), "l"(c)); return d;
}
__device__ __forceinline__ unsigned smem_u32(const void* p) {
    unsigned a;
    asm("{ .reg .u64 t; cvta.to.shared.u64 t, %1; cvt.u32.u64 %0, t; }"
        : "=r"(a) : "l"(p));
    return a;
}

// ---------------------------------------------------------------------------
// Kernel A: bx < 98 -> sf (R6 proven form).
//           bx >= 98 -> pool 16 channels, then (after per-batch rendezvous)
//                       compute the k2 MLP chunk cg = bx-98 for this batch.
// ---------------------------------------------------------------------------
__global__ void __launch_bounds__(512, 4) kA_sf_pool_cf(
    const float* __restrict__ x,
    const float* __restrict__ ws,
    const float* __restrict__ bs,
    const float* __restrict__ w1, const float* __restrict__ b1,
    const float* __restrict__ w2, const float* __restrict__ b2,
    const float* __restrict__ fn_std)
{
    __shared__ __align__(16) char sm[31232];   // 30.5 KB union

    const int b    = blockIdx.y;
    const int bx   = blockIdx.x;
    const int tid  = threadIdx.x;
    const int lane = tid & 31;
    const int w    = tid >> 5;

    if (bx >= 98) {
        // ===================== pool + k2 path =====================
        float* pooled_s = (float*)sm;                 // 1 KB
        float* y1_s     = (float*)(sm + 1024);        // 52 floats
        float* w2c      = (float*)(sm + 1280);        // 144*51*4 = 29376 B
        float* y2_s     = (float*)(sm + 1280 + 29376);// 576 B

        const int cg = bx - 98;                       // chunk == pool index

        // pool: warp w owns channel cg*16? No — channel (bx-98)*16+w
        {
            const int c = cg * 16 + w;
            const float4* p4 = (const float4*)(x + ((size_t)b * CC + c) * HW);
            float s = 0.f;
            for (int j = lane; j < 784; j += 32) {
                float4 v = __ldg(p4 + j);
                s += (v.x + v.y) + (v.z + v.w);
            }
#pragma unroll
            for (int o = 16; o > 0; o >>= 1) s += __shfl_xor_sync(0xffffffffu, s, o);
            if (lane == 0) {
                g_pooled[b * CC + c] = s * (1.f / (float)HW);
                __threadfence();              // publish before arrival
            }
        }
        __syncthreads();

        // arrive + stage w2 chunk (independent of pooled) + spin
        __shared__ unsigned tgt_s;
        if (tid == 0) {
            unsigned v = atomicAdd(&g_pcnt[b], 1u) + 1u;
            tgt_s = ((v + 15u) >> 4) << 4;    // next multiple of 16
        }
        {
            const float4* src = (const float4*)(w2 + (size_t)cg * 144 * MID);
#pragma unroll
            for (int i = tid; i < 144 * MID / 4; i += 512)
                ((float4*)w2c)[i] = __ldg(src + i);
        }
        __syncthreads();
        if (tid == 0) {
            unsigned tgt = tgt_s;
            while (*((volatile unsigned*)&g_pcnt[b]) < tgt) { }
            __threadfence();                  // acquire
        }
        __syncthreads();

        if (tid < CC) pooled_s[tid] = g_pooled[b * CC + tid];
        __syncthreads();

        // layer 1: 16 warps, warp j handles rows j, j+16, j+32
        for (int j = w; j < MID; j += 16) {
            const float* wr = w1 + j * CC;
            float s = 0.f;
#pragma unroll
            for (int k = 0; k < CC / 32; k++)
                s = fmaf(pooled_s[lane + k * 32], __ldg(wr + lane + k * 32), s);
#pragma unroll
            for (int o = 16; o > 0; o >>= 1) s += __shfl_xor_sync(0xffffffffu, s, o);
            if (lane == 0) y1_s[j] = fmaxf(s + __ldg(b1 + j), 0.f);
        }
        __syncthreads();

        if (tid < 144) {
            const int r = cg * 144 + tid;
            float a = __ldg(b2 + r);
            const float* row = w2c + tid * MID;
#pragma unroll
            for (int m = 0; m < MID; m++) a = fmaf(y1_s[m], row[m], a);
            y2_s[tid] = a;
        }
        __syncthreads();

        if (tid < 16) {
            const int c = cg * 16 + tid;
            float y[TAPS];
            float m = 0.f;
#pragma unroll
            for (int k = 0; k < TAPS; k++) { y[k] = y2_s[tid * TAPS + k]; m += y[k]; }
            m *= (1.f / 9.f);
            float ss = 0.f;
#pragma unroll
            for (int k = 0; k < TAPS; k++) { float d = y[k] - m; ss = fmaf(d, d, ss); }
            float inv = 1.f / (sqrtf(ss * (1.f / 8.f)) + 1e-10f);
#pragma unroll
            for (int k = 0; k < TAPS; k++)
                g_cf[(size_t)b * CKK + c * TAPS + k] =
                    (y[k] - m) * inv * __ldg(fn_std + c * TAPS + k);
        }
        return;
    }

    // ===================== sf path (R6 proven) =====================
    float* ws_s = (float*)sm;                 // 12 KB
    float* red  = (float*)(sm + 12288);       // 18 KB

#pragma unroll
    for (int i = tid; i < TAPS * CC; i += 512) {
        int n = i >> 8, c = i & 255;
        ws_s[c * 12 + n] = ws[i];
    }
    __syncthreads();

    const int pix = bx * 32 + lane;
    const float* xb = x + ((size_t)b * CC + w * 16) * HW + pix;

    float acc[TAPS];
#pragma unroll
    for (int n = 0; n < TAPS; n++) acc[n] = 0.f;

#pragma unroll
    for (int cc = 0; cc < 16; cc++) {
        float xv = __ldg(xb + (size_t)cc * HW);
        const float* wr = ws_s + (w * 16 + cc) * 12;
        float4 wa = *(const float4*)(wr);
        float4 wb = *(const float4*)(wr + 4);
        float  w8 = wr[8];
        acc[0] = fmaf(xv, wa.x, acc[0]);
        acc[1] = fmaf(xv, wa.y, acc[1]);
        acc[2] = fmaf(xv, wa.z, acc[2]);
        acc[3] = fmaf(xv, wa.w, acc[3]);
        acc[4] = fmaf(xv, wb.x, acc[4]);
        acc[5] = fmaf(xv, wb.y, acc[5]);
        acc[6] = fmaf(xv, wb.z, acc[6]);
        acc[7] = fmaf(xv, wb.w, acc[7]);
        acc[8] = fmaf(xv, w8,   acc[8]);
    }

#pragma unroll
    for (int n = 0; n < TAPS; n++)
        red[(w * TAPS + n) * 32 + lane] = acc[n];
    __syncthreads();

    if (tid < 32) {
        float a[TAPS];
        float m = 0.f;
#pragma unroll
        for (int n = 0; n < TAPS; n++) {
            float s = 0.f;
#pragma unroll
            for (int gg = 0; gg < 16; gg++) s += red[(gg * TAPS + n) * 32 + tid];
            a[n] = s + __ldg(bs + n);
            m += a[n];
        }
        m *= (1.f / 9.f);
        float ss = 0.f;
#pragma unroll
        for (int n = 0; n < TAPS; n++) { float d = a[n] - m; ss = fmaf(d, d, ss); }
        float inv = GAIN_OVER_K / (sqrtf(ss * (1.f / 8.f)) + 1e-10f);
        const int pix2 = bx * 32 + tid;
#pragma unroll
        for (int n = 0; n < TAPS; n++)
            g_sf[((size_t)b * TAPS + n) * HW + pix2] = (a[n] - m) * inv;
    }
}

// ---------------------------------------------------------------------------
// Kernel 3 (frozen, R11): DDF combine, bulk-copy halos, f32x2 math.
// ---------------------------------------------------------------------------
#define K3_CG 16
#define HSTR 56
#define HSZ  (10 * HSTR)     // 560
__global__ void __launch_bounds__(224) k3_ddf(
    const float* __restrict__ x, float* __restrict__ out)
{
    __shared__ __align__(16) float xraw[4 + K3_CG * HSZ + 4];
    __shared__ __align__(16) ull cf2_s[K3_CG * TAPS];
    __shared__ __align__(8)  ull mbar_st;

    float* const xh = xraw + 4;

    const int b  = blockIdx.z;
    const int cg = blockIdx.y;
    const int bx = blockIdx.x;
    const int r0 = bx * 8;
    const int tx = threadIdx.x;
    const int ty = threadIdx.y;
    const int tid = ty * 28 + tx;

    const int row = r0 + ty;
    const int col = 2 * tx;

    const unsigned mb = smem_u32(&mbar_st);
    const bool top = (bx == 0), bot = (bx == 6);
    const int nrows = 10 - (top ? 1 : 0) - (bot ? 1 : 0);
    const unsigned tx_bytes = (unsigned)(K3_CG * nrows * WW * 4);

    if (tid == 0)
        asm volatile("mbarrier.init.shared.b64 [%0], 1;" :: "r"(mb) : "memory");
    __syncthreads();
    if (tid == 0)
        asm volatile("mbarrier.arrive.expect_tx.shared.b64 _, [%0], %1;"
                     :: "r"(mb), "r"(tx_bytes) : "memory");
    __syncthreads();

    if (tid < K3_CG) {
        const int gr0    = top ? 0 : (r0 - 1);
        const int dst_rr = top ? 1 : 0;
        const float* src = x + ((size_t)(b * CC + cg * K3_CG + tid) * HW + gr0 * WW);
        const unsigned dst = smem_u32(xh + tid * HSZ + dst_rr * HSTR);
        asm volatile(
            "cp.async.bulk.shared::cta.global.mbarrier::complete_tx::bytes "
            "[%0], [%1], %2, [%3];"
            :: "r"(dst), "l"(src), "r"((unsigned)(nrows * WW * 4)), "r"(mb)
            : "memory");
    }

    if (tid < K3_CG * TAPS) {
        float v = g_cf[(size_t)b * CKK + cg * K3_CG * TAPS + tid];
        cf2_s[tid] = pack2(v, v);
    }

    ull sfr[TAPS];
    {
        const float* sp = g_sf + (size_t)b * TAPS * HW + row * WW + col;
#pragma unroll
        for (int n = 0; n < TAPS; n++)
            sfr[n] = __ldg((const ull*)(sp + n * HW));
    }

    if (top || bot) {
        const int zr = top ? 0 : 9;
        for (int i = tid; i < K3_CG * WW; i += 224) {
            int g = i / WW, j = i - g * WW;
            xh[g * HSZ + zr * HSTR + j] = 0.f;
        }
    }

    __syncthreads();
    {
        unsigned done;
        asm volatile(
            "{\n\t.reg .pred p;\n\t"
            "mbarrier.try_wait.parity.acquire.cta.shared::cta.b64 p, [%1], 0;\n\t"
            "selp.b32 %0, 1, 0, p;\n\t}"
            : "=r"(done) : "r"(mb) : "memory");
        if (!done) {
            asm volatile(
                "{\n\t.reg .pred P1;\n\t"
                "WL_%=:\n\t"
                "mbarrier.try_wait.parity.acquire.cta.shared::cta.b64 P1, [%0], 0, 0x989680;\n\t"
                "@P1 bra.uni WD_%=;\n\t"
                "bra.uni WL_%=;\n\t"
                "WD_%=:\n\t}"
                :: "r"(mb) : "memory");
        }
    }

    const bool eL = (tx == 0);
    const bool eR = (tx == 27);
    const float* hbase = xh + ty * HSTR + col;
    float* po = out + ((size_t)b * CC + cg * K3_CG) * HW + row * WW + col;

#pragma unroll
    for (int g = 0; g < K3_CG; g++) {
        const float* hp = hbase + g * HSZ;
        ull acc = 0ULL;
        const ull* cfp = cf2_s + g * TAPS;

#pragma unroll
        for (int u = 0; u < KK; u++) {
            const float* rp = hp + u * HSTR;
            ull A = *(const ull*)(rp - 2);
            ull Bv = *(const ull*)(rp);
            ull Cv = *(const ull*)(rp + 2);
            float al, ah, bl, bh, cl, ch;
            unpack2(A, al, ah);
            unpack2(Bv, bl, bh);
            unpack2(Cv, cl, ch);
            float xl = eL ? 0.f : ah;
            float xr = eR ? 0.f : cl;
            ull XL = pack2(xl, bl);
            ull XR = pack2(bh, xr);
            acc = fma2(XL, mul2(cfp[u * 3 + 0], sfr[u * 3 + 0]), acc);
            acc = fma2(Bv, mul2(cfp[u * 3 + 1], sfr[u * 3 + 1]), acc);
            acc = fma2(XR, mul2(cfp[u * 3 + 2], sfr[u * 3 + 2]), acc);
        }

        *(ull*)po = acc;
        po += HW;
    }
}

// ---------------------------------------------------------------------------
extern "C" void kernel_launch(void* const* d_in, const int* in_sizes, int n_in,
                              void* d_out, int out_size)
{
    const float* x      = (const float*)d_in[0];
    const float* w1     = (const float*)d_in[1];
    const float* b1     = (const float*)d_in[2];
    const float* w2     = (const float*)d_in[3];
    const float* b2     = (const float*)d_in[4];
    const float* ws     = (const float*)d_in[5];
    const float* bs     = (const float*)d_in[6];
    const float* fn_std = (const float*)d_in[7];
    float* out = (float*)d_out;

    dim3 gA(98 + 16, BB);            // 98 sf tiles + 16 pool+cf blocks per b
    kA_sf_pool_cf<<<gA, 512>>>(x, ws, bs, w1, b1, w2, b2, fn_std);

    dim3 g3(HH / 8, CC / K3_CG, BB);
    dim3 b3(28, 8);
    k3_ddf<<<g3, b3>>>(x, out);
}

// round 14
// speedup vs baseline: 1.0146x; 1.0146x over previous
#include <cuda_runtime.h>
#include <math.h>

#define BB 8
#define CC 256
#define HH 56
#define WW 56
#define HW (HH*WW)          // 3136
#define KK 3
#define TAPS 9
#define MID 51
#define CKK (CC*TAPS)       // 2304
#define GAIN_OVER_K 0.4714045207910317f   // sqrt(2)/3

__device__ __align__(16) float g_pooled[BB * CC];
__device__ __align__(16) float g_sf[BB * TAPS * HW];
__device__ __align__(16) float g_cf[BB * CKK];
__device__ unsigned g_pcnt[BB] = {0};

typedef unsigned long long ull;

// ---- f32x2 packed helpers (sm_103a) --------------------------------------
__device__ __forceinline__ ull pack2(float x, float y) {
    ull r; asm("mov.b64 %0, {%1, %2};" : "=l"(r) : "f"(x), "f"(y)); return r;
}
__device__ __forceinline__ void unpack2(ull v, float& x, float& y) {
    asm("mov.b64 {%0, %1}, %2;" : "=f"(x), "=f"(y) : "l"(v));
}
__device__ __forceinline__ ull mul2(ull a, ull b) {
    ull d; asm("mul.rn.f32x2 %0, %1, %2;" : "=l"(d) : "l"(a), "l"(b)); return d;
}
__device__ __forceinline__ ull fma2(ull a, ull b, ull c) {
    ull d; asm("fma.rn.f32x2 %0, %1, %2, %3;" : "=l"(d) : "l"(a), "l"(b), "l"(c)); return d;
}
__device__ __forceinline__ unsigned smem_u32(const void* p) {
    unsigned a;
    asm("{ .reg .u64 t; cvta.to.shared.u64 t, %1; cvt.u32.u64 %0, t; }"
        : "=r"(a) : "l"(p));
    return a;
}

// ---------------------------------------------------------------------------
// Kernel A (frozen R13): bx < 98 -> sf; bx >= 98 -> pool + fused k2 chunk.
// ---------------------------------------------------------------------------
__global__ void __launch_bounds__(512, 4) kA_sf_pool_cf(
    const float* __restrict__ x,
    const float* __restrict__ ws,
    const float* __restrict__ bs,
    const float* __restrict__ w1, const float* __restrict__ b1,
    const float* __restrict__ w2, const float* __restrict__ b2,
    const float* __restrict__ fn_std)
{
    __shared__ __align__(16) char sm[31232];

    const int b    = blockIdx.y;
    const int bx   = blockIdx.x;
    const int tid  = threadIdx.x;
    const int lane = tid & 31;
    const int w    = tid >> 5;

    if (bx >= 98) {
        float* pooled_s = (float*)sm;
        float* y1_s     = (float*)(sm + 1024);
        float* w2c      = (float*)(sm + 1280);
        float* y2_s     = (float*)(sm + 1280 + 29376);

        const int cg = bx - 98;

        {
            const int c = cg * 16 + w;
            const float4* p4 = (const float4*)(x + ((size_t)b * CC + c) * HW);
            float s = 0.f;
            for (int j = lane; j < 784; j += 32) {
                float4 v = __ldg(p4 + j);
                s += (v.x + v.y) + (v.z + v.w);
            }
#pragma unroll
            for (int o = 16; o > 0; o >>= 1) s += __shfl_xor_sync(0xffffffffu, s, o);
            if (lane == 0) {
                g_pooled[b * CC + c] = s * (1.f / (float)HW);
                __threadfence();
            }
        }
        __syncthreads();

        __shared__ unsigned tgt_s;
        if (tid == 0) {
            unsigned v = atomicAdd(&g_pcnt[b], 1u) + 1u;
            tgt_s = ((v + 15u) >> 4) << 4;
        }
        {
            const float4* src = (const float4*)(w2 + (size_t)cg * 144 * MID);
#pragma unroll
            for (int i = tid; i < 144 * MID / 4; i += 512)
                ((float4*)w2c)[i] = __ldg(src + i);
        }
        __syncthreads();
        if (tid == 0) {
            unsigned tgt = tgt_s;
            while (*((volatile unsigned*)&g_pcnt[b]) < tgt) { }
            __threadfence();
        }
        __syncthreads();

        if (tid < CC) pooled_s[tid] = g_pooled[b * CC + tid];
        __syncthreads();

        for (int j = w; j < MID; j += 16) {
            const float* wr = w1 + j * CC;
            float s = 0.f;
#pragma unroll
            for (int k = 0; k < CC / 32; k++)
                s = fmaf(pooled_s[lane + k * 32], __ldg(wr + lane + k * 32), s);
#pragma unroll
            for (int o = 16; o > 0; o >>= 1) s += __shfl_xor_sync(0xffffffffu, s, o);
            if (lane == 0) y1_s[j] = fmaxf(s + __ldg(b1 + j), 0.f);
        }
        __syncthreads();

        if (tid < 144) {
            const int r = cg * 144 + tid;
            float a = __ldg(b2 + r);
            const float* row = w2c + tid * MID;
#pragma unroll
            for (int m = 0; m < MID; m++) a = fmaf(y1_s[m], row[m], a);
            y2_s[tid] = a;
        }
        __syncthreads();

        if (tid < 16) {
            const int c = cg * 16 + tid;
            float y[TAPS];
            float m = 0.f;
#pragma unroll
            for (int k = 0; k < TAPS; k++) { y[k] = y2_s[tid * TAPS + k]; m += y[k]; }
            m *= (1.f / 9.f);
            float ss = 0.f;
#pragma unroll
            for (int k = 0; k < TAPS; k++) { float d = y[k] - m; ss = fmaf(d, d, ss); }
            float inv = 1.f / (sqrtf(ss * (1.f / 8.f)) + 1e-10f);
#pragma unroll
            for (int k = 0; k < TAPS; k++)
                g_cf[(size_t)b * CKK + c * TAPS + k] =
                    (y[k] - m) * inv * __ldg(fn_std + c * TAPS + k);
        }
        return;
    }

    float* ws_s = (float*)sm;
    float* red  = (float*)(sm + 12288);

#pragma unroll
    for (int i = tid; i < TAPS * CC; i += 512) {
        int n = i >> 8, c = i & 255;
        ws_s[c * 12 + n] = ws[i];
    }
    __syncthreads();

    const int pix = bx * 32 + lane;
    const float* xb = x + ((size_t)b * CC + w * 16) * HW + pix;

    float acc[TAPS];
#pragma unroll
    for (int n = 0; n < TAPS; n++) acc[n] = 0.f;

#pragma unroll
    for (int cc = 0; cc < 16; cc++) {
        float xv = __ldg(xb + (size_t)cc * HW);
        const float* wr = ws_s + (w * 16 + cc) * 12;
        float4 wa = *(const float4*)(wr);
        float4 wb = *(const float4*)(wr + 4);
        float  w8 = wr[8];
        acc[0] = fmaf(xv, wa.x, acc[0]);
        acc[1] = fmaf(xv, wa.y, acc[1]);
        acc[2] = fmaf(xv, wa.z, acc[2]);
        acc[3] = fmaf(xv, wa.w, acc[3]);
        acc[4] = fmaf(xv, wb.x, acc[4]);
        acc[5] = fmaf(xv, wb.y, acc[5]);
        acc[6] = fmaf(xv, wb.z, acc[6]);
        acc[7] = fmaf(xv, wb.w, acc[7]);
        acc[8] = fmaf(xv, w8,   acc[8]);
    }

#pragma unroll
    for (int n = 0; n < TAPS; n++)
        red[(w * TAPS + n) * 32 + lane] = acc[n];
    __syncthreads();

    if (tid < 32) {
        float a[TAPS];
        float m = 0.f;
#pragma unroll
        for (int n = 0; n < TAPS; n++) {
            float s = 0.f;
#pragma unroll
            for (int gg = 0; gg < 16; gg++) s += red[(gg * TAPS + n) * 32 + tid];
            a[n] = s + __ldg(bs + n);
            m += a[n];
        }
        m *= (1.f / 9.f);
        float ss = 0.f;
#pragma unroll
        for (int n = 0; n < TAPS; n++) { float d = a[n] - m; ss = fmaf(d, d, ss); }
        float inv = GAIN_OVER_K / (sqrtf(ss * (1.f / 8.f)) + 1e-10f);
        const int pix2 = bx * 32 + tid;
#pragma unroll
        for (int n = 0; n < TAPS; n++)
            g_sf[((size_t)b * TAPS + n) * HW + pix2] = (a[n] - m) * inv;
    }
}

// ---------------------------------------------------------------------------
// Kernel 3: 4-col threads. Block (14,8,2)=224; thread = 1 row x 4 cols,
// z splits the 16-channel loop (8 each). Bulk-copy halo (R11), f32x2 math.
// Per u-row: LDS.64 + LDS.128 + LDS.64 for 6 x-values feeding 4 outputs.
// ---------------------------------------------------------------------------
#define K3_CG 16
#define HSTR 56
#define HSZ  (10 * HSTR)     // 560
__global__ void __launch_bounds__(224) k3_ddf(
    const float* __restrict__ x, float* __restrict__ out)
{
    __shared__ __align__(16) float xraw[4 + K3_CG * HSZ + 4];
    __shared__ __align__(16) ull cf2_s[K3_CG * TAPS];
    __shared__ __align__(8)  ull mbar_st;

    float* const xh = xraw + 4;

    const int b  = blockIdx.z;
    const int cg = blockIdx.y;
    const int bx = blockIdx.x;
    const int r0 = bx * 8;
    const int tx = threadIdx.x;              // 0..13
    const int ty = threadIdx.y;              // 0..7
    const int tz = threadIdx.z;              // 0..1
    const int tid = (tz * 8 + ty) * 14 + tx;

    const int row  = r0 + ty;
    const int colb = 4 * tx;

    const unsigned mb = smem_u32(&mbar_st);
    const bool top = (bx == 0), bot = (bx == 6);
    const int nrows = 10 - (top ? 1 : 0) - (bot ? 1 : 0);
    const unsigned tx_bytes = (unsigned)(K3_CG * nrows * WW * 4);

    if (tid == 0)
        asm volatile("mbarrier.init.shared.b64 [%0], 1;" :: "r"(mb) : "memory");
    __syncthreads();
    if (tid == 0)
        asm volatile("mbarrier.arrive.expect_tx.shared.b64 _, [%0], %1;"
                     :: "r"(mb), "r"(tx_bytes) : "memory");
    __syncthreads();

    if (tid < K3_CG) {
        const int gr0    = top ? 0 : (r0 - 1);
        const int dst_rr = top ? 1 : 0;
        const float* src = x + ((size_t)(b * CC + cg * K3_CG + tid) * HW + gr0 * WW);
        const unsigned dst = smem_u32(xh + tid * HSZ + dst_rr * HSTR);
        asm volatile(
            "cp.async.bulk.shared::cta.global.mbarrier::complete_tx::bytes "
            "[%0], [%1], %2, [%3];"
            :: "r"(dst), "l"(src), "r"((unsigned)(nrows * WW * 4)), "r"(mb)
            : "memory");
    }

    if (tid < K3_CG * TAPS) {
        float v = g_cf[(size_t)b * CKK + cg * K3_CG * TAPS + tid];
        cf2_s[tid] = pack2(v, v);
    }

    // sf for this thread's 4 pixels (2 packed pairs) -> registers
    ull sfr0[TAPS], sfr1[TAPS];
    {
        const float* sp = g_sf + (size_t)b * TAPS * HW + row * WW + colb;
#pragma unroll
        for (int n = 0; n < TAPS; n++) {
            sfr0[n] = __ldg((const ull*)(sp + n * HW));
            sfr1[n] = __ldg((const ull*)(sp + n * HW + 2));
        }
    }

    if (top || bot) {
        const int zr = top ? 0 : 9;
        for (int i = tid; i < K3_CG * WW; i += 224) {
            int g = i / WW, j = i - g * WW;
            xh[g * HSZ + zr * HSTR + j] = 0.f;
        }
    }

    __syncthreads();
    {
        unsigned done;
        asm volatile(
            "{\n\t.reg .pred p;\n\t"
            "mbarrier.try_wait.parity.acquire.cta.shared::cta.b64 p, [%1], 0;\n\t"
            "selp.b32 %0, 1, 0, p;\n\t}"
            : "=r"(done) : "r"(mb) : "memory");
        if (!done) {
            asm volatile(
                "{\n\t.reg .pred P1;\n\t"
                "WL_%=:\n\t"
                "mbarrier.try_wait.parity.acquire.cta.shared::cta.b64 P1, [%0], 0, 0x989680;\n\t"
                "@P1 bra.uni WD_%=;\n\t"
                "bra.uni WL_%=;\n\t"
                "WD_%=:\n\t}"
                :: "r"(mb) : "memory");
        }
    }

    const bool eL = (tx == 0);
    const bool eR = (tx == 13);
    const float* hbase = xh + ty * HSTR + colb;
    float* po = out + ((size_t)b * CC + cg * K3_CG + tz * 8) * HW + row * WW + colb;

#pragma unroll
    for (int gi = 0; gi < 8; gi++) {
        const int g = tz * 8 + gi;
        const float* hp = hbase + g * HSZ;
        const ull* cfp = cf2_s + g * TAPS;
        ull acc0 = 0ULL, acc1 = 0ULL;

#pragma unroll
        for (int u = 0; u < KK; u++) {
            const float* rp = hp + u * HSTR;
            float2 Ap = *(const float2*)(rp - 2);     // colb-2, colb-1
            float4 Mv = *(const float4*)(rp);          // colb .. colb+3
            float2 Ep = *(const float2*)(rp + 4);      // colb+4, colb+5
            float xl = eL ? 0.f : Ap.y;
            float xr = eR ? 0.f : Ep.x;

            ull X00 = pack2(xl,   Mv.x);
            ull M01 = pack2(Mv.x, Mv.y);
            ull X02 = pack2(Mv.y, Mv.z);   // pair0 v2 == pair1 v0
            ull M23 = pack2(Mv.z, Mv.w);
            ull X12 = pack2(Mv.w, xr);

            ull c0 = cfp[u * 3 + 0];
            ull c1 = cfp[u * 3 + 1];
            ull c2 = cfp[u * 3 + 2];

            acc0 = fma2(X00, mul2(c0, sfr0[u * 3 + 0]), acc0);
            acc0 = fma2(M01, mul2(c1, sfr0[u * 3 + 1]), acc0);
            acc0 = fma2(X02, mul2(c2, sfr0[u * 3 + 2]), acc0);

            acc1 = fma2(X02, mul2(c0, sfr1[u * 3 + 0]), acc1);
            acc1 = fma2(M23, mul2(c1, sfr1[u * 3 + 1]), acc1);
            acc1 = fma2(X12, mul2(c2, sfr1[u * 3 + 2]), acc1);
        }

        float4 o;
        unpack2(acc0, o.x, o.y);
        unpack2(acc1, o.z, o.w);
        *(float4*)po = o;                 // STG.128, 16B aligned
        po += HW;
    }
}

// ---------------------------------------------------------------------------
extern "C" void kernel_launch(void* const* d_in, const int* in_sizes, int n_in,
                              void* d_out, int out_size)
{
    const float* x      = (const float*)d_in[0];
    const float* w1     = (const float*)d_in[1];
    const float* b1     = (const float*)d_in[2];
    const float* w2     = (const float*)d_in[3];
    const float* b2     = (const float*)d_in[4];
    const float* ws     = (const float*)d_in[5];
    const float* bs     = (const float*)d_in[6];
    const float* fn_std = (const float*)d_in[7];
    float* out = (float*)d_out;

    dim3 gA(98 + 16, BB);
    kA_sf_pool_cf<<<gA, 512>>>(x, ws, bs, w1, b1, w2, b2, fn_std);

    dim3 g3(HH / 8, CC / K3_CG, BB);
    dim3 b3(14, 8, 2);
    k3_ddf<<<g3, b3>>>(x, out);
}

// round 15
// speedup vs baseline: 1.1379x; 1.1214x over previous
#include <cuda_runtime.h>
#include <math.h>

#define BB 8
#define CC 256
#define HH 56
#define WW 56
#define HW (HH*WW)          // 3136
#define KK 3
#define TAPS 9
#define MID 51
#define CKK (CC*TAPS)       // 2304
#define GAIN_OVER_K 0.4714045207910317f   // sqrt(2)/3

#define NSF 98               // sf blocks per batch
#define NCF 16               // pool+cf blocks per batch
#define NDF 112              // ddf blocks per batch (7 row-tiles x 16 cgroups)
#define SF_END  (BB*NSF)     // 784
#define CF_END  (SF_END + BB*NCF)   // 912

__device__ __align__(16) float g_pooled[BB * CC];
__device__ __align__(16) float g_sf[BB * TAPS * HW];
__device__ __align__(16) float g_cf[BB * CKK];
__device__ unsigned g_pcnt[BB]  = {0};   // pooled arrivals (monotonic)
__device__ unsigned g_sfcnt[BB] = {0};   // sf-block completions
__device__ unsigned g_cfcnt[BB] = {0};   // cf-block completions
__device__ unsigned g_ddftkt[BB] = {0};  // ddf consumer tickets

typedef unsigned long long ull;

__device__ __forceinline__ ull pack2(float x, float y) {
    ull r; asm("mov.b64 %0, {%1, %2};" : "=l"(r) : "f"(x), "f"(y)); return r;
}
__device__ __forceinline__ void unpack2(ull v, float& x, float& y) {
    asm("mov.b64 {%0, %1}, %2;" : "=f"(x), "=f"(y) : "l"(v));
}
__device__ __forceinline__ ull mul2(ull a, ull b) {
    ull d; asm("mul.rn.f32x2 %0, %1, %2;" : "=l"(d) : "l"(a), "l"(b)); return d;
}
__device__ __forceinline__ ull fma2(ull a, ull b, ull c) {
    ull d; asm("fma.rn.f32x2 %0, %1, %2, %3;" : "=l"(d) : "l"(a), "l"(b), "l"(c)); return d;
}
__device__ __forceinline__ unsigned smem_u32(const void* p) {
    unsigned a;
    asm("{ .reg .u64 t; cvta.to.shared.u64 t, %1; cvt.u32.u64 %0, t; }"
        : "=r"(a) : "l"(p));
    return a;
}

#define K3_CG 16
#define HSTR 56
#define HSZ  (10 * HSTR)     // 560

// ---------------------------------------------------------------------------
// Mega-kernel: all three phases in one launch; cross-phase deps via
// replay-safe monotonic counters; ddf x-loads overlap the spin.
// ---------------------------------------------------------------------------
__global__ void __launch_bounds__(256, 6) mega(
    const float* __restrict__ x,
    const float* __restrict__ ws,
    const float* __restrict__ bs,
    const float* __restrict__ w1, const float* __restrict__ b1,
    const float* __restrict__ w2, const float* __restrict__ b2,
    const float* __restrict__ fn_std,
    float* __restrict__ out)
{
    __shared__ __align__(16) char sm[37056];
    __shared__ __align__(8)  ull mbar_st;
    __shared__ unsigned u0_s, u1_s;

    const int bid  = blockIdx.x;
    const int tid  = threadIdx.x;
    const int lane = tid & 31;
    const int w    = tid >> 5;

    if (bid < SF_END) {
        // ===================== sf block =====================
        const int b  = bid / NSF;
        const int bx = bid % NSF;
        float* ws_s = (float*)sm;                 // 12 KB
        float* red  = (float*)(sm + 12288);       // 9 KB

#pragma unroll
        for (int i = tid; i < TAPS * CC; i += 256) {
            int n = i >> 8, c = i & 255;
            ws_s[c * 12 + n] = ws[i];
        }
        __syncthreads();

        const int pix = bx * 32 + lane;
        const float* xb = x + ((size_t)b * CC + w * 32) * HW + pix;

        float acc[TAPS];
#pragma unroll
        for (int n = 0; n < TAPS; n++) acc[n] = 0.f;

#pragma unroll 8
        for (int cc = 0; cc < 32; cc++) {
            float xv = __ldg(xb + (size_t)cc * HW);
            const float* wr = ws_s + (w * 32 + cc) * 12;
            float4 wa = *(const float4*)(wr);
            float4 wb = *(const float4*)(wr + 4);
            float  w8 = wr[8];
            acc[0] = fmaf(xv, wa.x, acc[0]);
            acc[1] = fmaf(xv, wa.y, acc[1]);
            acc[2] = fmaf(xv, wa.z, acc[2]);
            acc[3] = fmaf(xv, wa.w, acc[3]);
            acc[4] = fmaf(xv, wb.x, acc[4]);
            acc[5] = fmaf(xv, wb.y, acc[5]);
            acc[6] = fmaf(xv, wb.z, acc[6]);
            acc[7] = fmaf(xv, wb.w, acc[7]);
            acc[8] = fmaf(xv, w8,   acc[8]);
        }

#pragma unroll
        for (int n = 0; n < TAPS; n++)
            red[(w * TAPS + n) * 32 + lane] = acc[n];
        __syncthreads();

        if (tid < 32) {
            float a[TAPS];
            float m = 0.f;
#pragma unroll
            for (int n = 0; n < TAPS; n++) {
                float s = 0.f;
#pragma unroll
                for (int gg = 0; gg < 8; gg++) s += red[(gg * TAPS + n) * 32 + tid];
                a[n] = s + __ldg(bs + n);
                m += a[n];
            }
            m *= (1.f / 9.f);
            float ss = 0.f;
#pragma unroll
            for (int n = 0; n < TAPS; n++) { float d = a[n] - m; ss = fmaf(d, d, ss); }
            float inv = GAIN_OVER_K / (sqrtf(ss * (1.f / 8.f)) + 1e-10f);
            const int pix2 = bx * 32 + tid;
#pragma unroll
            for (int n = 0; n < TAPS; n++)
                g_sf[((size_t)b * TAPS + n) * HW + pix2] = (a[n] - m) * inv;
            __threadfence();
        }
        __syncthreads();
        if (tid == 0) atomicAdd(&g_sfcnt[b], 1u);
        return;
    }

    if (bid < CF_END) {
        // ===================== pool + cf block =====================
        const int t  = bid - SF_END;
        const int b  = t / NCF;
        const int cg = t % NCF;

        float* pooled_s = (float*)sm;                  // 1 KB
        float* y1_s     = (float*)(sm + 1024);         // 256 B
        float* w2c      = (float*)(sm + 1280);         // 29376 B
        float* y2_s     = (float*)(sm + 1280 + 29376); // 576 B

        // pool 16 channels: warp w does channels cg*16 + w and + w + 8
#pragma unroll
        for (int h = 0; h < 2; h++) {
            const int c = cg * 16 + w + h * 8;
            const float4* p4 = (const float4*)(x + ((size_t)b * CC + c) * HW);
            float s = 0.f;
            for (int j = lane; j < 784; j += 32) {
                float4 v = __ldg(p4 + j);
                s += (v.x + v.y) + (v.z + v.w);
            }
#pragma unroll
            for (int o = 16; o > 0; o >>= 1) s += __shfl_xor_sync(0xffffffffu, s, o);
            if (lane == 0) g_pooled[b * CC + c] = s * (1.f / (float)HW);
        }
        if (lane == 0) __threadfence();
        __syncthreads();

        if (tid == 0) {
            unsigned v = atomicAdd(&g_pcnt[b], 1u) + 1u;
            u0_s = ((v + 15u) >> 4) << 4;      // rendezvous target
        }
        // stage w2 chunk (independent of pooled)
        {
            const float4* src = (const float4*)(w2 + (size_t)cg * 144 * MID);
#pragma unroll
            for (int i = tid; i < 144 * MID / 4; i += 256)
                ((float4*)w2c)[i] = __ldg(src + i);
        }
        __syncthreads();
        if (tid == 0) {
            unsigned tgt = u0_s;
            while (*((volatile unsigned*)&g_pcnt[b]) < tgt) __nanosleep(64);
            __threadfence();
        }
        __syncthreads();

        if (tid < CC) pooled_s[tid] = g_pooled[b * CC + tid];
        __syncthreads();

        for (int j = w; j < MID; j += 8) {
            const float* wr = w1 + j * CC;
            float s = 0.f;
#pragma unroll
            for (int k = 0; k < CC / 32; k++)
                s = fmaf(pooled_s[lane + k * 32], __ldg(wr + lane + k * 32), s);
#pragma unroll
            for (int o = 16; o > 0; o >>= 1) s += __shfl_xor_sync(0xffffffffu, s, o);
            if (lane == 0) y1_s[j] = fmaxf(s + __ldg(b1 + j), 0.f);
        }
        __syncthreads();

        if (tid < 144) {
            const int r = cg * 144 + tid;
            float a = __ldg(b2 + r);
            const float* row = w2c + tid * MID;
#pragma unroll
            for (int m = 0; m < MID; m++) a = fmaf(y1_s[m], row[m], a);
            y2_s[tid] = a;
        }
        __syncthreads();

        if (tid < 16) {
            const int c = cg * 16 + tid;
            float y[TAPS];
            float m = 0.f;
#pragma unroll
            for (int k = 0; k < TAPS; k++) { y[k] = y2_s[tid * TAPS + k]; m += y[k]; }
            m *= (1.f / 9.f);
            float ss = 0.f;
#pragma unroll
            for (int k = 0; k < TAPS; k++) { float d = y[k] - m; ss = fmaf(d, d, ss); }
            float inv = 1.f / (sqrtf(ss * (1.f / 8.f)) + 1e-10f);
#pragma unroll
            for (int k = 0; k < TAPS; k++)
                g_cf[(size_t)b * CKK + c * TAPS + k] =
                    (y[k] - m) * inv * __ldg(fn_std + c * TAPS + k);
            __threadfence();
        }
        __syncthreads();
        if (tid == 0) atomicAdd(&g_cfcnt[b], 1u);
        return;
    }

    // ===================== ddf block =====================
    {
        const int t   = bid - CF_END;
        const int b   = t / NDF;
        const int rem = t % NDF;
        const int cg  = rem / 7;
        const int bx  = rem % 7;
        const int r0  = bx * 8;

        float* const xh = (float*)(sm) + 4;           // 4-float front pad
        ull* cf2_s = (ull*)(sm + 35904);              // 1152 B (16B aligned)

        const int tx = tid % 28;
        const int ty = tid / 28;                       // 0..9; active < 8
        const bool act = (tid < 224);
        const int row = r0 + (act ? ty : 0);
        const int col = 2 * tx;

        const unsigned mb = smem_u32(&mbar_st);
        const bool top = (bx == 0), bot = (bx == 6);
        const int nrows = 10 - (top ? 1 : 0) - (bot ? 1 : 0);
        const unsigned tx_bytes = (unsigned)(K3_CG * nrows * WW * 4);

        if (tid == 0) {
            asm volatile("mbarrier.init.shared.b64 [%0], 1;" :: "r"(mb) : "memory");
            unsigned v = atomicAdd(&g_ddftkt[b], 1u);
            unsigned R = v / (unsigned)NDF;
            u0_s = (R + 1u) * (unsigned)NSF;   // sf target
            u1_s = (R + 1u) * (unsigned)NCF;   // cf target
        }
        __syncthreads();
        if (tid == 0)
            asm volatile("mbarrier.arrive.expect_tx.shared.b64 _, [%0], %1;"
                         :: "r"(mb), "r"(tx_bytes) : "memory");
        __syncthreads();

        // x bulk copies: input-only, overlap the spin below
        if (tid < K3_CG) {
            const int gr0    = top ? 0 : (r0 - 1);
            const int dst_rr = top ? 1 : 0;
            const float* src = x + ((size_t)(b * CC + cg * K3_CG + tid) * HW + gr0 * WW);
            const unsigned dst = smem_u32(xh + tid * HSZ + dst_rr * HSTR);
            asm volatile(
                "cp.async.bulk.shared::cta.global.mbarrier::complete_tx::bytes "
                "[%0], [%1], %2, [%3];"
                :: "r"(dst), "l"(src), "r"((unsigned)(nrows * WW * 4)), "r"(mb)
                : "memory");
        }

        if (top || bot) {
            const int zr = top ? 0 : 9;
            for (int i = tid; i < K3_CG * WW; i += 256) {
                int g = i / WW, j = i - g * WW;
                xh[g * HSZ + zr * HSTR + j] = 0.f;
            }
        }

        // spin until this batch's sf and cf are published
        if (tid == 0) {
            unsigned t0 = u0_s, t1 = u1_s;
            while (*((volatile unsigned*)&g_sfcnt[b]) < t0) __nanosleep(128);
            while (*((volatile unsigned*)&g_cfcnt[b]) < t1) __nanosleep(128);
            __threadfence();
        }
        __syncthreads();

        if (tid < K3_CG * TAPS) {
            float v = g_cf[(size_t)b * CKK + cg * K3_CG * TAPS + tid];
            cf2_s[tid] = pack2(v, v);
        }

        ull sfr[TAPS];
        if (act) {
            const float* sp = g_sf + (size_t)b * TAPS * HW + row * WW + col;
#pragma unroll
            for (int n = 0; n < TAPS; n++)
                sfr[n] = __ldg((const ull*)(sp + n * HW));
        }
        __syncthreads();   // cf2_s + edge zeros visible

        {
            unsigned done;
            asm volatile(
                "{\n\t.reg .pred p;\n\t"
                "mbarrier.try_wait.parity.acquire.cta.shared::cta.b64 p, [%1], 0;\n\t"
                "selp.b32 %0, 1, 0, p;\n\t}"
                : "=r"(done) : "r"(mb) : "memory");
            if (!done) {
                asm volatile(
                    "{\n\t.reg .pred P1;\n\t"
                    "WL_%=:\n\t"
                    "mbarrier.try_wait.parity.acquire.cta.shared::cta.b64 P1, [%0], 0, 0x989680;\n\t"
                    "@P1 bra.uni WD_%=;\n\t"
                    "bra.uni WL_%=;\n\t"
                    "WD_%=:\n\t}"
                    :: "r"(mb) : "memory");
            }
        }

        if (!act) return;

        const bool eL = (tx == 0);
        const bool eR = (tx == 27);
        const float* hbase = xh + ty * HSTR + col;
        float* po = out + ((size_t)b * CC + cg * K3_CG) * HW + row * WW + col;

#pragma unroll
        for (int g = 0; g < K3_CG; g++) {
            const float* hp = hbase + g * HSZ;
            ull acc = 0ULL;
            const ull* cfp = cf2_s + g * TAPS;

#pragma unroll
            for (int u = 0; u < KK; u++) {
                const float* rp = hp + u * HSTR;
                ull A  = *(const ull*)(rp - 2);
                ull Bv = *(const ull*)(rp);
                ull Cv = *(const ull*)(rp + 2);
                float al, ah, bl, bh, cl, ch;
                unpack2(A, al, ah);
                unpack2(Bv, bl, bh);
                unpack2(Cv, cl, ch);
                float xl = eL ? 0.f : ah;
                float xr = eR ? 0.f : cl;
                ull XL = pack2(xl, bl);
                ull XR = pack2(bh, xr);
                acc = fma2(XL, mul2(cfp[u * 3 + 0], sfr[u * 3 + 0]), acc);
                acc = fma2(Bv, mul2(cfp[u * 3 + 1], sfr[u * 3 + 1]), acc);
                acc = fma2(XR, mul2(cfp[u * 3 + 2], sfr[u * 3 + 2]), acc);
            }

            *(ull*)po = acc;
            po += HW;
        }
    }
}

// ---------------------------------------------------------------------------
extern "C" void kernel_launch(void* const* d_in, const int* in_sizes, int n_in,
                              void* d_out, int out_size)
{
    const float* x      = (const float*)d_in[0];
    const float* w1     = (const float*)d_in[1];
    const float* b1     = (const float*)d_in[2];
    const float* w2     = (const float*)d_in[3];
    const float* b2     = (const float*)d_in[4];
    const float* ws     = (const float*)d_in[5];
    const float* bs     = (const float*)d_in[6];
    const float* fn_std = (const float*)d_in[7];
    float* out = (float*)d_out;

    const int total = SF_END + BB * NCF + BB * NDF;   // 1808... (SF_END=784)
    mega<<<CF_END + BB * NDF, 256>>>(x, ws, bs, w1, b1, w2, b2, fn_std, out);
    (void)total;
}

// round 16
// speedup vs baseline: 1.1404x; 1.0022x over previous
#include <cuda_runtime.h>
#include <math.h>

#define BB 8
#define CC 256
#define HH 56
#define WW 56
#define HW (HH*WW)          // 3136
#define KK 3
#define TAPS 9
#define MID 51
#define CKK (CC*TAPS)       // 2304
#define GAIN_OVER_K 0.4714045207910317f   // sqrt(2)/3

#define NSF 98               // sf blocks per batch
#define NCF 16               // pool+cf blocks per batch
#define NDF 112              // ddf blocks per batch
#define SF_END  (BB*NSF)     // 784
#define CF_END  (SF_END + BB*NCF)   // 912

__device__ __align__(16) float g_pooled[BB * CC];
__device__ __align__(16) float g_sf[BB * TAPS * HW];
__device__ __align__(16) float g_cf[BB * CKK];
__device__ unsigned g_pcnt[BB]  = {0};
__device__ unsigned g_sfcnt[BB] = {0};
__device__ unsigned g_cfcnt[BB] = {0};
__device__ unsigned g_ddftkt[BB] = {0};

typedef unsigned long long ull;

__device__ __forceinline__ ull pack2(float x, float y) {
    ull r; asm("mov.b64 %0, {%1, %2};" : "=l"(r) : "f"(x), "f"(y)); return r;
}
__device__ __forceinline__ void unpack2(ull v, float& x, float& y) {
    asm("mov.b64 {%0, %1}, %2;" : "=f"(x), "=f"(y) : "l"(v));
}
__device__ __forceinline__ ull mul2(ull a, ull b) {
    ull d; asm("mul.rn.f32x2 %0, %1, %2;" : "=l"(d) : "l"(a), "l"(b)); return d;
}
__device__ __forceinline__ ull add2(ull a, ull b) {
    ull d; asm("add.rn.f32x2 %0, %1, %2;" : "=l"(d) : "l"(a), "l"(b)); return d;
}
__device__ __forceinline__ ull fma2(ull a, ull b, ull c) {
    ull d; asm("fma.rn.f32x2 %0, %1, %2, %3;" : "=l"(d) : "l"(a), "l"(b), "l"(c)); return d;
}
__device__ __forceinline__ unsigned smem_u32(const void* p) {
    unsigned a;
    asm("{ .reg .u64 t; cvta.to.shared.u64 t, %1; cvt.u32.u64 %0, t; }"
        : "=r"(a) : "l"(p));
    return a;
}

#define K3_CG 16
#define HSTR 56
#define HSZ  (10 * HSTR)     // 560

__global__ void __launch_bounds__(256, 6) mega(
    const float* __restrict__ x,
    const float* __restrict__ ws,
    const float* __restrict__ bs,
    const float* __restrict__ w1, const float* __restrict__ b1,
    const float* __restrict__ w2, const float* __restrict__ b2,
    const float* __restrict__ fn_std,
    float* __restrict__ out)
{
    __shared__ __align__(16) char sm[37056];
    __shared__ __align__(8)  ull mbar_st;
    __shared__ unsigned u0_s, u1_s;

    const int bid  = blockIdx.x;
    const int tid  = threadIdx.x;
    const int lane = tid & 31;
    const int w    = tid >> 5;

    if (bid < SF_END) {
        // ===================== sf block =====================
        const int b  = bid / NSF;
        const int bx = bid % NSF;
        float* ws_s = (float*)sm;
        float* red  = (float*)(sm + 12288);

#pragma unroll
        for (int i = tid; i < TAPS * CC; i += 256) {
            int n = i >> 8, c = i & 255;
            ws_s[c * 12 + n] = ws[i];
        }
        __syncthreads();

        const int pix = bx * 32 + lane;
        const float* xb = x + ((size_t)b * CC + w * 32) * HW + pix;

        float acc[TAPS];
#pragma unroll
        for (int n = 0; n < TAPS; n++) acc[n] = 0.f;

#pragma unroll 8
        for (int cc = 0; cc < 32; cc++) {
            float xv = __ldg(xb + (size_t)cc * HW);
            const float* wr = ws_s + (w * 32 + cc) * 12;
            float4 wa = *(const float4*)(wr);
            float4 wb = *(const float4*)(wr + 4);
            float  w8 = wr[8];
            acc[0] = fmaf(xv, wa.x, acc[0]);
            acc[1] = fmaf(xv, wa.y, acc[1]);
            acc[2] = fmaf(xv, wa.z, acc[2]);
            acc[3] = fmaf(xv, wa.w, acc[3]);
            acc[4] = fmaf(xv, wb.x, acc[4]);
            acc[5] = fmaf(xv, wb.y, acc[5]);
            acc[6] = fmaf(xv, wb.z, acc[6]);
            acc[7] = fmaf(xv, wb.w, acc[7]);
            acc[8] = fmaf(xv, w8,   acc[8]);
        }

#pragma unroll
        for (int n = 0; n < TAPS; n++)
            red[(w * TAPS + n) * 32 + lane] = acc[n];
        __syncthreads();

        if (tid < 32) {
            float a[TAPS];
            float m = 0.f;
#pragma unroll
            for (int n = 0; n < TAPS; n++) {
                float s = 0.f;
#pragma unroll
                for (int gg = 0; gg < 8; gg++) s += red[(gg * TAPS + n) * 32 + tid];
                a[n] = s + __ldg(bs + n);
                m += a[n];
            }
            m *= (1.f / 9.f);
            float ss = 0.f;
#pragma unroll
            for (int n = 0; n < TAPS; n++) { float d = a[n] - m; ss = fmaf(d, d, ss); }
            float inv = GAIN_OVER_K / (sqrtf(ss * (1.f / 8.f)) + 1e-10f);
            const int pix2 = bx * 32 + tid;
#pragma unroll
            for (int n = 0; n < TAPS; n++)
                g_sf[((size_t)b * TAPS + n) * HW + pix2] = (a[n] - m) * inv;
            __threadfence();
        }
        __syncthreads();
        if (tid == 0) atomicAdd(&g_sfcnt[b], 1u);
        return;
    }

    if (bid < CF_END) {
        // ===================== pool + cf block =====================
        const int t  = bid - SF_END;
        const int b  = t / NCF;
        const int cg = t % NCF;

        float* pooled_s = (float*)sm;
        float* y1_s     = (float*)(sm + 1024);
        float* w2c      = (float*)(sm + 1280);
        float* y2_s     = (float*)(sm + 1280 + 29376);

#pragma unroll
        for (int h = 0; h < 2; h++) {
            const int c = cg * 16 + w + h * 8;
            const float4* p4 = (const float4*)(x + ((size_t)b * CC + c) * HW);
            float s = 0.f;
            for (int j = lane; j < 784; j += 32) {
                float4 v = __ldg(p4 + j);
                s += (v.x + v.y) + (v.z + v.w);
            }
#pragma unroll
            for (int o = 16; o > 0; o >>= 1) s += __shfl_xor_sync(0xffffffffu, s, o);
            if (lane == 0) g_pooled[b * CC + c] = s * (1.f / (float)HW);
        }
        if (lane == 0) __threadfence();
        __syncthreads();

        if (tid == 0) {
            unsigned v = atomicAdd(&g_pcnt[b], 1u) + 1u;
            u0_s = ((v + 15u) >> 4) << 4;
        }
        {
            const float4* src = (const float4*)(w2 + (size_t)cg * 144 * MID);
#pragma unroll
            for (int i = tid; i < 144 * MID / 4; i += 256)
                ((float4*)w2c)[i] = __ldg(src + i);
        }
        __syncthreads();
        if (tid == 0) {
            unsigned tgt = u0_s;
            while (*((volatile unsigned*)&g_pcnt[b]) < tgt) __nanosleep(64);
            __threadfence();
        }
        __syncthreads();

        if (tid < CC) pooled_s[tid] = g_pooled[b * CC + tid];
        __syncthreads();

        for (int j = w; j < MID; j += 8) {
            const float* wr = w1 + j * CC;
            float s = 0.f;
#pragma unroll
            for (int k = 0; k < CC / 32; k++)
                s = fmaf(pooled_s[lane + k * 32], __ldg(wr + lane + k * 32), s);
#pragma unroll
            for (int o = 16; o > 0; o >>= 1) s += __shfl_xor_sync(0xffffffffu, s, o);
            if (lane == 0) y1_s[j] = fmaxf(s + __ldg(b1 + j), 0.f);
        }
        __syncthreads();

        if (tid < 144) {
            const int r = cg * 144 + tid;
            float a = __ldg(b2 + r);
            const float* row = w2c + tid * MID;
#pragma unroll
            for (int m = 0; m < MID; m++) a = fmaf(y1_s[m], row[m], a);
            y2_s[tid] = a;
        }
        __syncthreads();

        if (tid < 16) {
            const int c = cg * 16 + tid;
            float y[TAPS];
            float m = 0.f;
#pragma unroll
            for (int k = 0; k < TAPS; k++) { y[k] = y2_s[tid * TAPS + k]; m += y[k]; }
            m *= (1.f / 9.f);
            float ss = 0.f;
#pragma unroll
            for (int k = 0; k < TAPS; k++) { float d = y[k] - m; ss = fmaf(d, d, ss); }
            float inv = 1.f / (sqrtf(ss * (1.f / 8.f)) + 1e-10f);
#pragma unroll
            for (int k = 0; k < TAPS; k++)
                g_cf[(size_t)b * CKK + c * TAPS + k] =
                    (y[k] - m) * inv * __ldg(fn_std + c * TAPS + k);
            __threadfence();
        }
        __syncthreads();
        if (tid == 0) atomicAdd(&g_cfcnt[b], 1u);
        return;
    }

    // ===================== ddf block =====================
    {
        const int t   = bid - CF_END;
        const int b   = t / NDF;
        const int rem = t % NDF;
        const int cg  = rem / 7;
        const int bx  = rem % 7;
        const int r0  = bx * 8;

        float* const xh = (float*)(sm) + 4;
        ull* cf2_s = (ull*)(sm + 35904);

        const int tx = tid % 28;
        const int ty = tid / 28;
        const bool act = (tid < 224);
        const int row = r0 + (act ? ty : 0);
        const int col = 2 * tx;

        const unsigned mb = smem_u32(&mbar_st);
        const bool top = (bx == 0), bot = (bx == 6);
        const int nrows = 10 - (top ? 1 : 0) - (bot ? 1 : 0);
        const unsigned tx_bytes = (unsigned)(K3_CG * nrows * WW * 4);

        if (tid == 0) {
            asm volatile("mbarrier.init.shared.b64 [%0], 1;" :: "r"(mb) : "memory");
            unsigned v = atomicAdd(&g_ddftkt[b], 1u);
            unsigned R = v / (unsigned)NDF;
            u0_s = (R + 1u) * (unsigned)NSF;
            u1_s = (R + 1u) * (unsigned)NCF;
        }
        __syncthreads();
        if (tid == 0)
            asm volatile("mbarrier.arrive.expect_tx.shared.b64 _, [%0], %1;"
                         :: "r"(mb), "r"(tx_bytes) : "memory");
        __syncthreads();

        // x bulk copies: input-only, overlap the spins below
        if (tid < K3_CG) {
            const int gr0    = top ? 0 : (r0 - 1);
            const int dst_rr = top ? 1 : 0;
            const float* src = x + ((size_t)(b * CC + cg * K3_CG + tid) * HW + gr0 * WW);
            const unsigned dst = smem_u32(xh + tid * HSZ + dst_rr * HSTR);
            asm volatile(
                "cp.async.bulk.shared::cta.global.mbarrier::complete_tx::bytes "
                "[%0], [%1], %2, [%3];"
                :: "r"(dst), "l"(src), "r"((unsigned)(nrows * WW * 4)), "r"(mb)
                : "memory");
        }

        if (top || bot) {
            const int zr = top ? 0 : 9;
            for (int i = tid; i < K3_CG * WW; i += 256) {
                int g = i / WW, j = i - g * WW;
                xh[g * HSZ + zr * HSTR + j] = 0.f;
            }
        }

        // spin 1: sf published -> issue sfr loads -> spin 2: cf published
        if (tid == 0) {
            unsigned t0 = u0_s;
            while (*((volatile unsigned*)&g_sfcnt[b]) < t0) __nanosleep(128);
            __threadfence();
        }
        __syncthreads();

        ull sfr[TAPS];
        if (act) {
            const float* sp = g_sf + (size_t)b * TAPS * HW + row * WW + col;
#pragma unroll
            for (int n = 0; n < TAPS; n++)
                sfr[n] = __ldg((const ull*)(sp + n * HW));
        }

        if (tid == 0) {
            unsigned t1 = u1_s;
            while (*((volatile unsigned*)&g_cfcnt[b]) < t1) __nanosleep(128);
            __threadfence();
        }
        __syncthreads();

        if (tid < K3_CG * TAPS) {
            float v = g_cf[(size_t)b * CKK + cg * K3_CG * TAPS + tid];
            cf2_s[tid] = pack2(v, v);
        }
        __syncthreads();   // cf2_s + edge zeros visible

        {
            unsigned done;
            asm volatile(
                "{\n\t.reg .pred p;\n\t"
                "mbarrier.try_wait.parity.acquire.cta.shared::cta.b64 p, [%1], 0;\n\t"
                "selp.b32 %0, 1, 0, p;\n\t}"
                : "=r"(done) : "r"(mb) : "memory");
            if (!done) {
                asm volatile(
                    "{\n\t.reg .pred P1;\n\t"
                    "WL_%=:\n\t"
                    "mbarrier.try_wait.parity.acquire.cta.shared::cta.b64 P1, [%0], 0, 0x989680;\n\t"
                    "@P1 bra.uni WD_%=;\n\t"
                    "bra.uni WL_%=;\n\t"
                    "WD_%=:\n\t}"
                    :: "r"(mb) : "memory");
            }
        }

        if (!act) return;

        const bool eL = (tx == 0);
        const bool eR = (tx == 27);
        const float* hbase = xh + ty * HSTR + col;
        float* po = out + ((size_t)b * CC + cg * K3_CG) * HW + row * WW + col;

#pragma unroll
        for (int g = 0; g < K3_CG; g++) {
            const float* hp = hbase + g * HSZ;
            const ull* cfp = cf2_s + g * TAPS;
            // 3 independent accumulator chains (one per tap row)
            ull acc_u[KK];

#pragma unroll
            for (int u = 0; u < KK; u++) {
                const float* rp = hp + u * HSTR;
                ull A  = *(const ull*)(rp - 2);
                ull Bv = *(const ull*)(rp);
                ull Cv = *(const ull*)(rp + 2);
                float al, ah, bl, bh, cl, ch;
                unpack2(A, al, ah);
                unpack2(Bv, bl, bh);
                unpack2(Cv, cl, ch);
                float xl = eL ? 0.f : ah;
                float xr = eR ? 0.f : cl;
                ull XL = pack2(xl, bl);
                ull XR = pack2(bh, xr);
                ull a = mul2(XL, mul2(cfp[u * 3 + 0], sfr[u * 3 + 0]));
                a = fma2(Bv, mul2(cfp[u * 3 + 1], sfr[u * 3 + 1]), a);
                a = fma2(XR, mul2(cfp[u * 3 + 2], sfr[u * 3 + 2]), a);
                acc_u[u] = a;
            }

            ull acc = add2(add2(acc_u[0], acc_u[1]), acc_u[2]);
            *(ull*)po = acc;
            po += HW;
        }
    }
}

// ---------------------------------------------------------------------------
extern "C" void kernel_launch(void* const* d_in, const int* in_sizes, int n_in,
                              void* d_out, int out_size)
{
    const float* x      = (const float*)d_in[0];
    const float* w1     = (const float*)d_in[1];
    const float* b1     = (const float*)d_in[2];
    const float* w2     = (const float*)d_in[3];
    const float* b2     = (const float*)d_in[4];
    const float* ws     = (const float*)d_in[5];
    const float* bs     = (const float*)d_in[6];
    const float* fn_std = (const float*)d_in[7];
    float* out = (float*)d_out;

    mega<<<CF_END + BB * NDF, 256>>>(x, ws, bs, w1, b1, w2, b2, fn_std, out);
}